// round 13
// baseline (speedup 1.0000x reference)
#include <cuda_runtime.h>
#include <cuda_bf16.h>
#include <math.h>

// Problem constants: B=2, L=512 (both sides), Dh=1024, P=64, C = 4P+1 = 257
#define NB    2
#define LSEQ  512
#define DH    1024
#define PP    64
#define NCH   257
#define PLANE (LSEQ*LSEQ)      // 262144 floats per channel plane
#define PLANE4 (PLANE/4)
#define NROWS (NB*LSEQ)        // 1024 rows per side
#define NKC   16               // K chunks in projection (64 wide each)
#define HPITCH 68              // h_s row pitch in floats (272B = 17 float4, aligned)

// Scratch (device globals; no allocation allowed)
__device__ float g_part[NKC * 2 * NROWS * PP]; // [kc][side][row][p]  (8MB)
__device__ float g_za [NROWS*PP];              // side a: [b*512+i][p]
__device__ float g_zbT[NB*PP*LSEQ];            // side b: [b][p][j]
__device__ float g_na [NROWS];
__device__ float g_nb [NROWS];

__device__ __forceinline__ float gelu_exact(float x) {
    return 0.5f * x * (1.0f + erff(x * 0.7071067811865476f));
}

// ---------------------------------------------------------------------------
// Kernel A1: partial projection GEMM over a 64-wide K chunk.  [R5 exact]
// Register-blocked 4 rows x 4 p per thread; block 256 = 64 rows x 64 p.
// grid (16 rowgroups, 2 sides, 16 kchunks) = 512 blocks.
// ---------------------------------------------------------------------------
__global__ __launch_bounds__(256) void proj_partial(
    const float* __restrict__ h_a, const float* __restrict__ h_b,
    const float* __restrict__ Wa,  const float* __restrict__ Wb)
{
    const int side = blockIdx.y;
    const int kc   = blockIdx.z;                 // 0..15, K chunk of 64
    const float* __restrict__ H  = side ? h_b : h_a;
    const float* __restrict__ Wp = side ? Wb  : Wa;

    const int tid = threadIdx.x;
    const int tx = tid & 15;                     // p-quad 0..15
    const int ty = tid >> 4;                     // row-quad 0..15
    const int rowBase = blockIdx.x * 64;

    __shared__ float  h_s[64 * HPITCH];          // [k][row]  (~17.4KB)
    __shared__ float4 w_s[64 * 16];              // [k][p4]    (16KB)

    // Load h chunk (64 rows x 16 float4 along k) transposed into h_s.
    {
        const float4* __restrict__ H4 = (const float4*)H;   // [row][256]
        #pragma unroll
        for (int it = 0; it < 4; ++it) {
            int idx = tid + it * 256;            // 0..1023
            int r   = idx >> 4;                  // row in tile 0..63
            int c4  = idx & 15;                  // float4 index along k
            float4 v = H4[(size_t)(rowBase + r) * 256 + kc * 16 + c4];
            h_s[(4*c4 + 0) * HPITCH + r] = v.x;
            h_s[(4*c4 + 1) * HPITCH + r] = v.y;
            h_s[(4*c4 + 2) * HPITCH + r] = v.z;
            h_s[(4*c4 + 3) * HPITCH + r] = v.w;
        }
    }
    // Load W chunk (64 k x 16 float4), coalesced, layout [k][p4].
    {
        const float4* __restrict__ W4 = (const float4*)Wp;  // [1024][16]
        #pragma unroll
        for (int it = 0; it < 4; ++it) {
            int idx = tid + it * 256;            // 0..1023
            int k   = idx >> 4;
            int p4  = idx & 15;
            w_s[idx] = W4[(size_t)(kc * 64 + k) * 16 + p4];
        }
    }
    __syncthreads();

    float4 acc0 = make_float4(0.f,0.f,0.f,0.f);
    float4 acc1 = make_float4(0.f,0.f,0.f,0.f);
    float4 acc2 = make_float4(0.f,0.f,0.f,0.f);
    float4 acc3 = make_float4(0.f,0.f,0.f,0.f);

    #pragma unroll 8
    for (int k = 0; k < 64; ++k) {
        float4 h4 = *(const float4*)&h_s[k * HPITCH + ty * 4];  // 4 rows
        float4 w4 = w_s[k * 16 + tx];                           // 4 p
        acc0.x += h4.x*w4.x; acc0.y += h4.x*w4.y; acc0.z += h4.x*w4.z; acc0.w += h4.x*w4.w;
        acc1.x += h4.y*w4.x; acc1.y += h4.y*w4.y; acc1.z += h4.y*w4.z; acc1.w += h4.y*w4.w;
        acc2.x += h4.z*w4.x; acc2.y += h4.z*w4.y; acc2.z += h4.z*w4.z; acc2.w += h4.z*w4.w;
        acc3.x += h4.w*w4.x; acc3.y += h4.w*w4.y; acc3.z += h4.w*w4.z; acc3.w += h4.w*w4.w;
    }

    float4* P4 = ((float4*)g_part) + (((size_t)kc * 2 + side) * NROWS) * 16;
    const int r0 = rowBase + ty * 4;
    P4[(size_t)(r0 + 0) * 16 + tx] = acc0;
    P4[(size_t)(r0 + 1) * 16 + tx] = acc1;
    P4[(size_t)(r0 + 2) * 16 + tx] = acc2;
    P4[(size_t)(r0 + 3) * 16 + tx] = acc3;
}

// ---------------------------------------------------------------------------
// Kernel A2: reduce 16 partials, bias + exact GELU, per-row norm, layouts.
// grid (128, 2), block (16,8). [R5 exact]
// ---------------------------------------------------------------------------
__global__ __launch_bounds__(128) void reduce_gelu(
    const float* __restrict__ ba, const float* __restrict__ bb)
{
    const int side = blockIdx.y;
    const float* __restrict__ bp = side ? bb : ba;
    const int tx = threadIdx.x;
    const int ty = threadIdx.y;
    const int row = blockIdx.x * 8 + ty;

    const float4* P4 = (const float4*)g_part;
    float4 a = P4[(((size_t)0 * 2 + side) * NROWS + row) * 16 + tx];
    #pragma unroll
    for (int c = 1; c < NKC; ++c) {
        float4 v = P4[(((size_t)c * 2 + side) * NROWS + row) * 16 + tx];
        a.x += v.x; a.y += v.y; a.z += v.z; a.w += v.w;
    }
    const float4 bias4 = ((const float4*)bp)[tx];

    float4 z;
    z.x = gelu_exact(a.x + bias4.x);
    z.y = gelu_exact(a.y + bias4.y);
    z.z = gelu_exact(a.z + bias4.z);
    z.w = gelu_exact(a.w + bias4.w);

    float ss = z.x*z.x + z.y*z.y + z.z*z.z + z.w*z.w;
    ss += __shfl_xor_sync(0xFFFFFFFFu, ss, 1, 16);
    ss += __shfl_xor_sync(0xFFFFFFFFu, ss, 2, 16);
    ss += __shfl_xor_sync(0xFFFFFFFFu, ss, 4, 16);
    ss += __shfl_xor_sync(0xFFFFFFFFu, ss, 8, 16);

    if (side == 0) {
        ((float4*)g_za)[(size_t)row * 16 + tx] = z;
        if (tx == 0) g_na[row] = sqrtf(ss + 1e-8f);
    } else {
        const int b = row >> 9;
        const int j = row & 511;
        const int p0 = tx * 4;
        float* dst = g_zbT + ((size_t)(b * PP + p0)) * LSEQ + j;
        dst[0*LSEQ] = z.x;
        dst[1*LSEQ] = z.y;
        dst[2*LSEQ] = z.z;
        dst[3*LSEQ] = z.w;
        if (tx == 0) g_nb[row] = sqrtf(ss + 1e-8f);
    }
}

// ---------------------------------------------------------------------------
// Kernel B: full [B, 257, LA, LB] output — R5 structure EXACTLY, with ONE
// change: __stcs (evict-first, still L2-allocating) -> __stwt (write-through
// to DRAM). All stores are full 128B-coalesced sectors, so write-through
// halves LTS-side work per output byte (no dirty-line writeback pass).
// ---------------------------------------------------------------------------
__global__ __launch_bounds__(128) void interact_kernel(float* __restrict__ out)
{
    const int i = blockIdx.x;       // 0..511
    const int b = blockIdx.y;       // 0..1
    const int t = threadIdx.x;      // 0..127, covers j = 4t .. 4t+3

    __shared__ float za_s[PP];
    __shared__ float na_s;
    if (t < PP) za_s[t] = g_za[((size_t)(b * LSEQ + i)) * PP + t];
    if (t == 0) na_s = g_na[b * LSEQ + i];
    __syncthreads();

    const float4 nb4 = *(const float4*)&g_nb[b * LSEQ + 4 * t];

    float4* O = ((float4*)out) + (size_t)b * NCH * PLANE4 + (size_t)i * (LSEQ/4) + t;
    const float4* ZBT = ((const float4*)(g_zbT + (size_t)b * PP * LSEQ)) + t;

    float4 dot = make_float4(0.f, 0.f, 0.f, 0.f);

    #pragma unroll 4
    for (int p = 0; p < PP; ++p) {
        float4 zb = __ldg(ZBT + p * (LSEQ/4));
        float  za = za_s[p];
        float4* o = O + (size_t)p * PLANE4;

        __stwt(o,                          make_float4(za, za, za, za));
        __stwt(o + (size_t) 64 * PLANE4,   zb);
        __stwt(o + (size_t)128 * PLANE4,
               make_float4(fabsf(za - zb.x), fabsf(za - zb.y),
                           fabsf(za - zb.z), fabsf(za - zb.w)));
        __stwt(o + (size_t)192 * PLANE4,
               make_float4(za * zb.x, za * zb.y, za * zb.z, za * zb.w));

        dot.x += za * zb.x; dot.y += za * zb.y;
        dot.z += za * zb.z; dot.w += za * zb.w;
    }

    const float inv_na = 1.0f / na_s;
    float4 sim = make_float4(dot.x * inv_na / nb4.x,
                             dot.y * inv_na / nb4.y,
                             dot.z * inv_na / nb4.z,
                             dot.w * inv_na / nb4.w);
    __stwt(O + (size_t)256 * PLANE4, sim);
}

extern "C" void kernel_launch(void* const* d_in, const int* in_sizes, int n_in,
                              void* d_out, int out_size)
{
    const float* h_a = (const float*)d_in[0];
    const float* h_b = (const float*)d_in[1];
    const float* Wa  = (const float*)d_in[2];
    const float* ba  = (const float*)d_in[3];
    const float* Wb  = (const float*)d_in[4];
    const float* bb  = (const float*)d_in[5];
    float* out = (float*)d_out;

    proj_partial<<<dim3(16, 2, NKC), 256>>>(h_a, h_b, Wa, Wb);
    reduce_gelu <<<dim3(128, 2),     dim3(16, 8)>>>(ba, bb);
    interact_kernel<<<dim3(LSEQ, NB), 128>>>(out);
}

// round 14
// speedup vs baseline: 1.0525x; 1.0525x over previous
#include <cuda_runtime.h>
#include <cuda_bf16.h>
#include <math.h>

// Problem constants: B=2, L=512 (both sides), Dh=1024, P=64, C = 4P+1 = 257
#define NB    2
#define LSEQ  512
#define DH    1024
#define PP    64
#define NCH   257
#define PLANE (LSEQ*LSEQ)      // 262144 floats per channel plane
#define PLANE4 (PLANE/4)
#define NROWS (NB*LSEQ)        // 1024 rows per side
#define NKC   32               // K chunks in projection (32 wide each)
#define HPITCH 36              // h_s row pitch in floats (144B = 9 float4, aligned)

// Scratch (device globals; no allocation allowed)
__device__ float g_part[NKC * 2 * NROWS * PP]; // [kc][side][row][p]  (16MB)
__device__ float g_za [NROWS*PP];              // side a: [b*512+i][p]
__device__ float g_zbT[NB*PP*LSEQ];            // side b: [b][p][j]
__device__ float g_na [NROWS];
__device__ float g_nb [NROWS];

__device__ __forceinline__ float gelu_exact(float x) {
    return 0.5f * x * (1.0f + erff(x * 0.7071067811865476f));
}

// ---------------------------------------------------------------------------
// Kernel A1: partial projection GEMM over a 32-wide K chunk. [R11 exact —
// measured-best proj config: 13.63us]. 4 rows x 4 p register tile, 128-thread
// blocks covering 32 rows x 64 p. grid (32, 2, 32) = 2048 blocks.
// ---------------------------------------------------------------------------
__global__ __launch_bounds__(128) void proj_partial(
    const float* __restrict__ h_a, const float* __restrict__ h_b,
    const float* __restrict__ Wa,  const float* __restrict__ Wb)
{
    const int side = blockIdx.y;
    const int kc   = blockIdx.z;                 // 0..31, K chunk of 32
    const float* __restrict__ H  = side ? h_b : h_a;
    const float* __restrict__ Wp = side ? Wb  : Wa;

    const int tid = threadIdx.x;                 // 0..127
    const int tx = tid & 15;                     // p-quad 0..15
    const int ty = tid >> 4;                     // row-quad 0..7
    const int rowBase = blockIdx.x * 32;

    __shared__ float  h_s[32 * HPITCH];          // [k][row]  (~4.6KB)
    __shared__ float4 w_s[32 * 16];              // [k][p4]    (8KB)

    // Load h chunk (32 rows x 8 float4 along k) transposed into h_s.
    {
        const float4* __restrict__ H4 = (const float4*)H;   // [row][256]
        #pragma unroll
        for (int it = 0; it < 2; ++it) {
            int idx = tid + it * 128;            // 0..255
            int r   = idx >> 3;                  // row in tile 0..31
            int c4  = idx & 7;                   // float4 index along k (0..7)
            float4 v = H4[(size_t)(rowBase + r) * 256 + kc * 8 + c4];
            h_s[(4*c4 + 0) * HPITCH + r] = v.x;
            h_s[(4*c4 + 1) * HPITCH + r] = v.y;
            h_s[(4*c4 + 2) * HPITCH + r] = v.z;
            h_s[(4*c4 + 3) * HPITCH + r] = v.w;
        }
    }
    // Load W chunk (32 k x 16 float4), coalesced, layout [k][p4].
    {
        const float4* __restrict__ W4 = (const float4*)Wp;  // [1024][16]
        #pragma unroll
        for (int it = 0; it < 4; ++it) {
            int idx = tid + it * 128;            // 0..511
            int k   = idx >> 4;
            int p4  = idx & 15;
            w_s[idx] = W4[(size_t)(kc * 32 + k) * 16 + p4];
        }
    }
    __syncthreads();

    float4 acc0 = make_float4(0.f,0.f,0.f,0.f);
    float4 acc1 = make_float4(0.f,0.f,0.f,0.f);
    float4 acc2 = make_float4(0.f,0.f,0.f,0.f);
    float4 acc3 = make_float4(0.f,0.f,0.f,0.f);

    #pragma unroll 8
    for (int k = 0; k < 32; ++k) {
        float4 h4 = *(const float4*)&h_s[k * HPITCH + ty * 4];  // 4 rows
        float4 w4 = w_s[k * 16 + tx];                           // 4 p
        acc0.x += h4.x*w4.x; acc0.y += h4.x*w4.y; acc0.z += h4.x*w4.z; acc0.w += h4.x*w4.w;
        acc1.x += h4.y*w4.x; acc1.y += h4.y*w4.y; acc1.z += h4.y*w4.z; acc1.w += h4.y*w4.w;
        acc2.x += h4.z*w4.x; acc2.y += h4.z*w4.y; acc2.z += h4.z*w4.z; acc2.w += h4.z*w4.w;
        acc3.x += h4.w*w4.x; acc3.y += h4.w*w4.y; acc3.z += h4.w*w4.z; acc3.w += h4.w*w4.w;
    }

    float4* P4 = ((float4*)g_part) + (((size_t)kc * 2 + side) * NROWS) * 16;
    const int r0 = rowBase + ty * 4;
    P4[(size_t)(r0 + 0) * 16 + tx] = acc0;
    P4[(size_t)(r0 + 1) * 16 + tx] = acc1;
    P4[(size_t)(r0 + 2) * 16 + tx] = acc2;
    P4[(size_t)(r0 + 3) * 16 + tx] = acc3;
}

// ---------------------------------------------------------------------------
// Kernel A2: reduce 32 partials, bias + exact GELU, per-row norm, layouts.
// NEW: 512-thread blocks — the kc-sum is split across 4 thread-groups (8
// loads each) with an smem cross-group reduction, giving 4x the memory
// parallelism of the old latency-bound version. grid (128, 2).
// ---------------------------------------------------------------------------
__global__ __launch_bounds__(512) void reduce_gelu(
    const float* __restrict__ ba, const float* __restrict__ bb)
{
    const int side = blockIdx.y;
    const float* __restrict__ bp = side ? bb : ba;
    const int tid = threadIdx.x;            // 0..511
    const int tx = tid & 15;                // p-quad
    const int ty = (tid >> 4) & 7;          // row in 8-row tile
    const int kg = tid >> 7;                // kc group 0..3
    const int row = blockIdx.x * 8 + ty;

    const float4* P4 = (const float4*)g_part;
    float4 a = make_float4(0.f, 0.f, 0.f, 0.f);
    #pragma unroll
    for (int c = kg * 8; c < kg * 8 + 8; ++c) {
        float4 v = P4[(((size_t)c * 2 + side) * NROWS + row) * 16 + tx];
        a.x += v.x; a.y += v.y; a.z += v.z; a.w += v.w;
    }

    __shared__ float4 red_s[4][8][16];      // 8KB
    if (kg > 0) red_s[kg][ty][tx] = a;
    __syncthreads();
    if (kg != 0) return;

    {
        float4 v1 = red_s[1][ty][tx];
        float4 v2 = red_s[2][ty][tx];
        float4 v3 = red_s[3][ty][tx];
        a.x += v1.x + v2.x + v3.x;
        a.y += v1.y + v2.y + v3.y;
        a.z += v1.z + v2.z + v3.z;
        a.w += v1.w + v2.w + v3.w;
    }
    const float4 bias4 = ((const float4*)bp)[tx];

    float4 z;
    z.x = gelu_exact(a.x + bias4.x);
    z.y = gelu_exact(a.y + bias4.y);
    z.z = gelu_exact(a.z + bias4.z);
    z.w = gelu_exact(a.w + bias4.w);

    float ss = z.x*z.x + z.y*z.y + z.z*z.z + z.w*z.w;
    ss += __shfl_xor_sync(0xFFFFFFFFu, ss, 1, 16);
    ss += __shfl_xor_sync(0xFFFFFFFFu, ss, 2, 16);
    ss += __shfl_xor_sync(0xFFFFFFFFu, ss, 4, 16);
    ss += __shfl_xor_sync(0xFFFFFFFFu, ss, 8, 16);

    if (side == 0) {
        ((float4*)g_za)[(size_t)row * 16 + tx] = z;
        if (tx == 0) g_na[row] = sqrtf(ss + 1e-8f);
    } else {
        const int b = row >> 9;
        const int j = row & 511;
        const int p0 = tx * 4;
        float* dst = g_zbT + ((size_t)(b * PP + p0)) * LSEQ + j;
        dst[0*LSEQ] = z.x;
        dst[1*LSEQ] = z.y;
        dst[2*LSEQ] = z.z;
        dst[3*LSEQ] = z.w;
        if (tx == 0) g_nb[row] = sqrtf(ss + 1e-8f);
    }
}

// ---------------------------------------------------------------------------
// Kernel B: full [B, 257, LA, LB] output — R5 EXACT (best measured, __stcs).
// One block per (i, b). 128 threads, each owns 4 consecutive j. Per channel p:
// one coalesced LDG.128 of zbT row + four STG.128 streaming stores; dot for
// the cosine channel accumulated in-register; sim plane stored at the end.
// ---------------------------------------------------------------------------
__global__ __launch_bounds__(128) void interact_kernel(float* __restrict__ out)
{
    const int i = blockIdx.x;       // 0..511
    const int b = blockIdx.y;       // 0..1
    const int t = threadIdx.x;      // 0..127, covers j = 4t .. 4t+3

    __shared__ float za_s[PP];
    __shared__ float na_s;
    if (t < PP) za_s[t] = g_za[((size_t)(b * LSEQ + i)) * PP + t];
    if (t == 0) na_s = g_na[b * LSEQ + i];
    __syncthreads();

    const float4 nb4 = *(const float4*)&g_nb[b * LSEQ + 4 * t];

    float4* O = ((float4*)out) + (size_t)b * NCH * PLANE4 + (size_t)i * (LSEQ/4) + t;
    const float4* ZBT = ((const float4*)(g_zbT + (size_t)b * PP * LSEQ)) + t;

    float4 dot = make_float4(0.f, 0.f, 0.f, 0.f);

    #pragma unroll 4
    for (int p = 0; p < PP; ++p) {
        float4 zb = __ldg(ZBT + p * (LSEQ/4));
        float  za = za_s[p];
        float4* o = O + (size_t)p * PLANE4;

        __stcs(o,                          make_float4(za, za, za, za));
        __stcs(o + (size_t) 64 * PLANE4,   zb);
        __stcs(o + (size_t)128 * PLANE4,
               make_float4(fabsf(za - zb.x), fabsf(za - zb.y),
                           fabsf(za - zb.z), fabsf(za - zb.w)));
        __stcs(o + (size_t)192 * PLANE4,
               make_float4(za * zb.x, za * zb.y, za * zb.z, za * zb.w));

        dot.x += za * zb.x; dot.y += za * zb.y;
        dot.z += za * zb.z; dot.w += za * zb.w;
    }

    const float inv_na = 1.0f / na_s;
    float4 sim = make_float4(dot.x * inv_na / nb4.x,
                             dot.y * inv_na / nb4.y,
                             dot.z * inv_na / nb4.z,
                             dot.w * inv_na / nb4.w);
    __stcs(O + (size_t)256 * PLANE4, sim);
}

extern "C" void kernel_launch(void* const* d_in, const int* in_sizes, int n_in,
                              void* d_out, int out_size)
{
    const float* h_a = (const float*)d_in[0];
    const float* h_b = (const float*)d_in[1];
    const float* Wa  = (const float*)d_in[2];
    const float* ba  = (const float*)d_in[3];
    const float* Wb  = (const float*)d_in[4];
    const float* bb  = (const float*)d_in[5];
    float* out = (float*)d_out;

    proj_partial<<<dim3(32, 2, NKC), 128>>>(h_a, h_b, Wa, Wb);
    reduce_gelu <<<dim3(128, 2),     512>>>(ba, bb);
    interact_kernel<<<dim3(LSEQ, NB), 128>>>(out);
}